// round 1
// baseline (speedup 1.0000x reference)
#include <cuda_runtime.h>
#include <math.h>

#define NROWS 8192
#define DIM   128
#define CHUNK 64
#define NBLK  (NROWS / CHUNK)          // 128 partial-gram blocks
#define ULL_PER_GRAM (DIM * DIM / 2)   // 8192 ull = 16384 floats
#define RED_BLOCKS 64
#define SMEM_BYTES (2 * CHUNK * DIM * 4 + 2 * CHUNK * 4)  // 66048

// Partial Grams: [chunk_block][gram 0=QQ,1=KK,2=QK][thread-permuted 8192 ull]
__device__ unsigned long long g_part[NBLK][3][ULL_PER_GRAM];
__device__ double g_bsum[RED_BLOCKS];

// ---- f32x2 packed helpers -------------------------------------------------
__device__ __forceinline__ void fma2(unsigned long long& acc,
                                     unsigned long long a,
                                     unsigned long long b) {
    asm("fma.rn.f32x2 %0, %1, %2, %0;" : "+l"(acc) : "l"(a), "l"(b));
}
__device__ __forceinline__ unsigned long long pack2(float lo, float hi) {
    unsigned long long r;
    asm("mov.b64 %0, {%1, %2};" : "=l"(r)
        : "r"(__float_as_uint(lo)), "r"(__float_as_uint(hi)));
    return r;
}
__device__ __forceinline__ unsigned long long splat2(float x) {
    unsigned long long r;
    unsigned u = __float_as_uint(x);
    asm("mov.b64 %0, {%1, %1};" : "=l"(r) : "r"(u));
    return r;
}

// ---- kernel 1: normalize slab + 3 partial 128x128 Grams -------------------
extern "C" __global__ void __launch_bounds__(256, 1)
gram_kernel(const float* __restrict__ Q, const float* __restrict__ K)
{
    extern __shared__ float sm[];
    float* sQ    = sm;                         // [CHUNK][DIM]
    float* sK    = sm + CHUNK * DIM;           // [CHUNK][DIM]
    float* sInvQ = sK + CHUNK * DIM;           // [CHUNK]
    float* sInvK = sInvQ + CHUNK;              // [CHUNK]

    const int tid  = threadIdx.x;
    const int lane = tid & 31;
    const int warp = tid >> 5;
    const int blk  = blockIdx.x;

    const float4* Qg = reinterpret_cast<const float4*>(Q + (size_t)blk * CHUNK * DIM);
    const float4* Kg = reinterpret_cast<const float4*>(K + (size_t)blk * CHUNK * DIM);

    // Load slab into registers. float4 index tid + i*256: warp w at iter i
    // covers exactly row (w + 8*i): 32 lanes * 16B = 512B = one full row.
    float4 q4[8], k4[8];
#pragma unroll
    for (int i = 0; i < 8; i++) {
        q4[i] = Qg[tid + i * 256];
        k4[i] = Kg[tid + i * 256];
    }

    // Row sum-of-squares via warp shfl reduce (no smem conflicts).
#pragma unroll
    for (int i = 0; i < 8; i++) {
        float sq = q4[i].x * q4[i].x + q4[i].y * q4[i].y
                 + q4[i].z * q4[i].z + q4[i].w * q4[i].w;
        float sk = k4[i].x * k4[i].x + k4[i].y * k4[i].y
                 + k4[i].z * k4[i].z + k4[i].w * k4[i].w;
#pragma unroll
        for (int off = 16; off > 0; off >>= 1) {
            sq += __shfl_xor_sync(0xffffffffu, sq, off);
            sk += __shfl_xor_sync(0xffffffffu, sk, off);
        }
        if (lane == 0) {
            int row = warp + i * 8;
            sInvQ[row] = 1.0f / fmaxf(sqrtf(sq), 1e-8f);
            sInvK[row] = 1.0f / fmaxf(sqrtf(sk), 1e-8f);
        }
    }
    __syncthreads();

    // Scale and stage normalized slab into smem (coalesced float4 stores).
#pragma unroll
    for (int i = 0; i < 8; i++) {
        int row = warp + i * 8;
        float iq = sInvQ[row], ik = sInvK[row];
        float4 a = q4[i]; a.x *= iq; a.y *= iq; a.z *= iq; a.w *= iq;
        float4 b = k4[i]; b.x *= ik; b.y *= ik; b.z *= ik; b.w *= ik;
        reinterpret_cast<float4*>(sQ)[tid + i * 256] = a;
        reinterpret_cast<float4*>(sK)[tid + i * 256] = b;
    }
    __syncthreads();

    // Thread (ty,tx) owns output tile d in [ty*8, ty*8+8), e in [tx*8, tx*8+8).
    const int tx = tid & 15;
    const int ty = tid >> 4;
    const int aoff = ty * 8;
    const int boff = tx * 8;

    // ---- pass 1: Gq = Qn^T Qn  and  Gqk = Qn^T Kn (share the 'a' operand) --
    {
        unsigned long long accQ[8][4], accX[8][4];
#pragma unroll
        for (int d = 0; d < 8; d++)
#pragma unroll
            for (int j = 0; j < 4; j++) { accQ[d][j] = 0ull; accX[d][j] = 0ull; }

        for (int k = 0; k < CHUNK; k++) {
            const float* rQ = sQ + k * DIM;
            const float* rK = sK + k * DIM;
            float4 a0 = *reinterpret_cast<const float4*>(rQ + aoff);
            float4 a1 = *reinterpret_cast<const float4*>(rQ + aoff + 4);
            float4 b0 = *reinterpret_cast<const float4*>(rQ + boff);
            float4 b1 = *reinterpret_cast<const float4*>(rQ + boff + 4);
            float4 c0 = *reinterpret_cast<const float4*>(rK + boff);
            float4 c1 = *reinterpret_cast<const float4*>(rK + boff + 4);
            unsigned long long qb[4] = { pack2(b0.x, b0.y), pack2(b0.z, b0.w),
                                         pack2(b1.x, b1.y), pack2(b1.z, b1.w) };
            unsigned long long kb[4] = { pack2(c0.x, c0.y), pack2(c0.z, c0.w),
                                         pack2(c1.x, c1.y), pack2(c1.z, c1.w) };
            float av[8] = { a0.x, a0.y, a0.z, a0.w, a1.x, a1.y, a1.z, a1.w };
#pragma unroll
            for (int d = 0; d < 8; d++) {
                unsigned long long pa = splat2(av[d]);
#pragma unroll
                for (int j = 0; j < 4; j++) {
                    fma2(accQ[d][j], pa, qb[j]);
                    fma2(accX[d][j], pa, kb[j]);
                }
            }
        }
        // Thread-private permuted layout: 32 contiguous ull per thread.
        unsigned long long* pq = &g_part[blk][0][(size_t)tid * 32];
        unsigned long long* px = &g_part[blk][2][(size_t)tid * 32];
#pragma unroll
        for (int d = 0; d < 8; d++)
#pragma unroll
            for (int j = 0; j < 4; j++) {
                pq[d * 4 + j] = accQ[d][j];
                px[d * 4 + j] = accX[d][j];
            }
    }

    // ---- pass 2: Gk = Kn^T Kn ---------------------------------------------
    {
        unsigned long long accK[8][4];
#pragma unroll
        for (int d = 0; d < 8; d++)
#pragma unroll
            for (int j = 0; j < 4; j++) accK[d][j] = 0ull;

        for (int k = 0; k < CHUNK; k++) {
            const float* rK = sK + k * DIM;
            float4 a0 = *reinterpret_cast<const float4*>(rK + aoff);
            float4 a1 = *reinterpret_cast<const float4*>(rK + aoff + 4);
            float4 c0 = *reinterpret_cast<const float4*>(rK + boff);
            float4 c1 = *reinterpret_cast<const float4*>(rK + boff + 4);
            unsigned long long kb[4] = { pack2(c0.x, c0.y), pack2(c0.z, c0.w),
                                         pack2(c1.x, c1.y), pack2(c1.z, c1.w) };
            float av[8] = { a0.x, a0.y, a0.z, a0.w, a1.x, a1.y, a1.z, a1.w };
#pragma unroll
            for (int d = 0; d < 8; d++) {
                unsigned long long pa = splat2(av[d]);
#pragma unroll
                for (int j = 0; j < 4; j++) fma2(accK[d][j], pa, kb[j]);
            }
        }
        unsigned long long* pk = &g_part[blk][1][(size_t)tid * 32];
#pragma unroll
        for (int d = 0; d < 8; d++)
#pragma unroll
            for (int j = 0; j < 4; j++) pk[d * 4 + j] = accK[d][j];
    }
}

// ---- kernel 2: sum partials across chunks, square, combine ----------------
extern "C" __global__ void __launch_bounds__(256)
reduce_kernel()
{
    const int idx = blockIdx.x * 256 + threadIdx.x;   // [0, 16384)
    const float* base = reinterpret_cast<const float*>(g_part);
    // float view layout: [b][3][16384]
    double sq = 0.0, sk = 0.0, sx = 0.0;
#pragma unroll 4
    for (int b = 0; b < NBLK; b++) {
        const float* p = base + (size_t)b * 3 * 16384;
        sq += (double)p[idx];
        sk += (double)p[16384 + idx];
        sx += (double)p[32768 + idx];
    }
    double c = sq * sq + sk * sk - 2.0 * sx * sx;

#pragma unroll
    for (int off = 16; off > 0; off >>= 1)
        c += __shfl_xor_sync(0xffffffffu, c, off);

    __shared__ double wsum[8];
    if ((threadIdx.x & 31) == 0) wsum[threadIdx.x >> 5] = c;
    __syncthreads();
    if (threadIdx.x == 0) {
        double t = 0.0;
#pragma unroll
        for (int w = 0; w < 8; w++) t += wsum[w];
        g_bsum[blockIdx.x] = t;
    }
}

// ---- kernel 3: final scalar ----------------------------------------------
extern "C" __global__ void final_kernel(float* out)
{
    double s = g_bsum[threadIdx.x] + g_bsum[threadIdx.x + 32];
#pragma unroll
    for (int off = 16; off > 0; off >>= 1)
        s += __shfl_xor_sync(0xffffffffu, s, off);
    if (threadIdx.x == 0)
        out[0] = (float)(s / (8192.0 * 8191.0));
}

extern "C" void kernel_launch(void* const* d_in, const int* in_sizes, int n_in,
                              void* d_out, int out_size)
{
    (void)in_sizes; (void)n_in; (void)out_size;
    const float* Q = (const float*)d_in[0];
    const float* K = (const float*)d_in[1];

    cudaFuncSetAttribute(gram_kernel,
                         cudaFuncAttributeMaxDynamicSharedMemorySize, SMEM_BYTES);

    gram_kernel<<<NBLK, 256, SMEM_BYTES>>>(Q, K);
    reduce_kernel<<<RED_BLOCKS, 256>>>();
    final_kernel<<<1, 32>>>((float*)d_out);
}

// round 4
// speedup vs baseline: 2.0425x; 2.0425x over previous
#include <cuda_runtime.h>
#include <cuda_bf16.h>
#include <cstdint>
#include <math.h>

#define NROWS   8192
#define DIM     128
#define KSLAB   128                  // K-rows per gram block
#define NSLAB   (NROWS / KSLAB)      // 64
#define RED_BLOCKS 64

// ---------------- device globals (no allocs allowed) ----------------------
__device__ __nv_bfloat16 g_qt[DIM * NROWS];    // QT[d][r], row-major 128x8192
__device__ __nv_bfloat16 g_kt[DIM * NROWS];    // KT[d][r]
__device__ float  g_part[3][NSLAB][DIM * DIM]; // partial grams (permuted layout)
__device__ double g_bsum[RED_BLOCKS];

__device__ __forceinline__ uint32_t smem_u32(const void* p) {
    uint32_t a;
    asm("{ .reg .u64 t; cvta.to.shared.u64 t, %1; cvt.u32.u64 %0, t; }"
        : "=r"(a) : "l"(p));
    return a;
}

#define LDMX4(r0, r1, r2, r3, addr) \
    asm volatile("ldmatrix.sync.aligned.m8n8.x4.shared.b16 {%0,%1,%2,%3}, [%4];" \
        : "=r"(r0), "=r"(r1), "=r"(r2), "=r"(r3) : "r"(addr))

#define MMA16816(d, a, b) \
    asm volatile("mma.sync.aligned.m16n8k16.row.col.f32.bf16.bf16.f32 " \
        "{%0,%1,%2,%3}, {%4,%5,%6,%7}, {%8,%9}, {%0,%1,%2,%3};" \
        : "+f"((d)[0]), "+f"((d)[1]), "+f"((d)[2]), "+f"((d)[3]) \
        : "r"((a)[0]), "r"((a)[1]), "r"((a)[2]), "r"((a)[3]), \
          "r"((b)[0]), "r"((b)[1]))

// ---- kernel 1: row-normalize + transpose to bf16 --------------------------
// grid = 256: mat = bx>>7 (0=Q,1=K), slab of 64 rows = bx&127. block = 256 thr.
#define CONV_ROWS 64
#define CONV_PITCH 129
#define CONV_SMEM (CONV_ROWS * CONV_PITCH * 4 + CONV_ROWS * 4)

extern "C" __global__ void __launch_bounds__(256)
conv_kernel(const float* __restrict__ Q, const float* __restrict__ K)
{
    extern __shared__ float sm[];
    float* sT   = sm;                              // [64][129] raw f32
    float* sInv = sm + CONV_ROWS * CONV_PITCH;     // [64]

    const int t    = threadIdx.x;
    const int lane = t & 31;
    const int mat  = blockIdx.x >> 7;
    const int slab = blockIdx.x & 127;

    const float* src = (mat ? K : Q) + (size_t)slab * CONV_ROWS * DIM;
    __nv_bfloat16* dst = mat ? g_kt : g_qt;

    // load 64x128 f32 tile; warp w at iter i owns row i*8+w fully
#pragma unroll
    for (int i = 0; i < 8; i++) {
        int f4 = i * 256 + t;                 // row = f4>>5, c4 = f4&31
        int row = f4 >> 5, c4 = f4 & 31;
        float4 v = reinterpret_cast<const float4*>(src)[f4];
        float* p = sT + row * CONV_PITCH + c4 * 4;
        p[0] = v.x; p[1] = v.y; p[2] = v.z; p[3] = v.w;
        float s = v.x * v.x + v.y * v.y + v.z * v.z + v.w * v.w;
#pragma unroll
        for (int off = 16; off > 0; off >>= 1)
            s += __shfl_xor_sync(0xffffffffu, s, off);
        if (lane == 0)
            sInv[row] = 1.0f / fmaxf(sqrtf(s), 1e-8f);
    }
    __syncthreads();

    // write transposed bf16: dst[d][slab*64 + r], pairs of r per thread
#pragma unroll
    for (int i = 0; i < 16; i++) {
        int idx = i * 256 + t;                // d = idx>>5, rp = idx&31
        int d = idx >> 5, rp = idx & 31;
        int r0 = rp * 2, r1 = rp * 2 + 1;
        float v0 = sT[r0 * CONV_PITCH + d] * sInv[r0];
        float v1 = sT[r1 * CONV_PITCH + d] * sInv[r1];
        __nv_bfloat162 h = __floats2bfloat162_rn(v0, v1);
        *reinterpret_cast<__nv_bfloat162*>(
            &dst[(size_t)d * NROWS + slab * CONV_ROWS + r0]) = h;
    }
}

// ---- kernel 2: mma.sync partial grams -------------------------------------
// grid = 192: gram = bx>>6 (0=QQ,1=KK,2=QK), slab = bx&63. block = 256 thr.
// smem tiles: [128 rows][PITCH=136 bf16]; pitch 17x16B -> ldmatrix conflict-free
#define PITCH 136
#define TILE_BYTES (DIM * PITCH * 2)           // 34816
#define GRAM_SMEM  (2 * TILE_BYTES)            // 69632

extern "C" __global__ void __launch_bounds__(256)
gram_kernel()
{
    extern __shared__ char smem[];
    const uint32_t sA = smem_u32(smem);
    const uint32_t sB = sA + TILE_BYTES;
    __nv_bfloat16* hA = reinterpret_cast<__nv_bfloat16*>(smem);
    __nv_bfloat16* hB = hA + DIM * PITCH;

    const int t    = threadIdx.x;
    const int lane = t & 31;
    const int w    = t >> 5;
    const int gram = blockIdx.x >> 6;
    const int slab = blockIdx.x & 63;

    const __nv_bfloat16* srcA = (gram == 1) ? g_kt : g_qt;
    const __nv_bfloat16* srcB = (gram == 0) ? g_qt : g_kt;

    // load 128x128 bf16 tiles (16B chunks): 2048 chunks, 8 iters x 256 thr
#pragma unroll
    for (int i = 0; i < 8; i++) {
        int g   = i * 256 + t;
        int row = g >> 4, c16 = g & 15;
        uint4 va = *reinterpret_cast<const uint4*>(
            &srcA[(size_t)row * NROWS + slab * KSLAB + c16 * 8]);
        uint4 vb = *reinterpret_cast<const uint4*>(
            &srcB[(size_t)row * NROWS + slab * KSLAB + c16 * 8]);
        *reinterpret_cast<uint4*>(&hA[row * PITCH + c16 * 8]) = va;
        *reinterpret_cast<uint4*>(&hB[row * PITCH + c16 * 8]) = vb;
    }
    __syncthreads();

    // warp tile: wm = w&3 -> 32 M-rows, wn = w>>2 -> 64 N-cols
    const int m0 = (w & 3) * 32;
    const int n0 = (w >> 2) * 64;

    // ldmatrix lane address components
    const int aRow  = m0 + (lane & 15);
    const int aKoff = (lane >> 4) * 8;
    const int bNoff = (lane & 7) + ((lane >> 4) & 1) * 8;
    const int bKoff = ((lane >> 3) & 1) * 8;

    float acc[2][8][4];
#pragma unroll
    for (int mt = 0; mt < 2; mt++)
#pragma unroll
        for (int nt = 0; nt < 8; nt++)
#pragma unroll
            for (int r = 0; r < 4; r++) acc[mt][nt][r] = 0.0f;

#pragma unroll
    for (int ks = 0; ks < 8; ks++) {
        const int k0 = ks * 16;
        uint32_t a[2][4];
#pragma unroll
        for (int mt = 0; mt < 2; mt++) {
            uint32_t addr = sA + (uint32_t)(((aRow + mt * 16) * PITCH)
                                            + k0 + aKoff) * 2;
            LDMX4(a[mt][0], a[mt][1], a[mt][2], a[mt][3], addr);
        }
        uint32_t b[8][2];
#pragma unroll
        for (int nt4 = 0; nt4 < 4; nt4++) {
            uint32_t addr = sB + (uint32_t)(((n0 + nt4 * 16 + bNoff) * PITCH)
                                            + k0 + bKoff) * 2;
            uint32_t r0, r1, r2, r3;
            LDMX4(r0, r1, r2, r3, addr);
            b[nt4 * 2][0] = r0;     b[nt4 * 2][1] = r1;
            b[nt4 * 2 + 1][0] = r2; b[nt4 * 2 + 1][1] = r3;
        }
#pragma unroll
        for (int mt = 0; mt < 2; mt++)
#pragma unroll
            for (int nt = 0; nt < 8; nt++)
                MMA16816(acc[mt][nt], a[mt], b[nt]);
    }

    // permuted-coalesced partial store (identical permutation for all blocks)
    float* out = &g_part[gram][slab][0];
#pragma unroll
    for (int mt = 0; mt < 2; mt++)
#pragma unroll
        for (int nt = 0; nt < 8; nt++)
#pragma unroll
            for (int r = 0; r < 4; r++)
                out[w * 2048 + (mt * 8 + nt) * 128 + r * 32 + lane]
                    = acc[mt][nt][r];
}

// ---- kernel 3: sum slabs, combine ----------------------------------------
extern "C" __global__ void __launch_bounds__(256)
reduce_kernel()
{
    const int idx = blockIdx.x * 256 + threadIdx.x;   // [0, 16384)
    const float* p0 = &g_part[0][0][0];
    const float* p1 = &g_part[1][0][0];
    const float* p2 = &g_part[2][0][0];
    double sq = 0.0, sk = 0.0, sx = 0.0;
#pragma unroll 8
    for (int s = 0; s < NSLAB; s++) {
        sq += (double)p0[s * 16384 + idx];
        sk += (double)p1[s * 16384 + idx];
        sx += (double)p2[s * 16384 + idx];
    }
    double c = sq * sq + sk * sk - 2.0 * sx * sx;

#pragma unroll
    for (int off = 16; off > 0; off >>= 1)
        c += __shfl_xor_sync(0xffffffffu, c, off);

    __shared__ double wsum[8];
    if ((threadIdx.x & 31) == 0) wsum[threadIdx.x >> 5] = c;
    __syncthreads();
    if (threadIdx.x == 0) {
        double s = 0.0;
#pragma unroll
        for (int ww = 0; ww < 8; ww++) s += wsum[ww];
        g_bsum[blockIdx.x] = s;
    }
}

// ---- kernel 4: final scalar ----------------------------------------------
extern "C" __global__ void final_kernel(float* out)
{
    double s = g_bsum[threadIdx.x] + g_bsum[threadIdx.x + 32];
#pragma unroll
    for (int off = 16; off > 0; off >>= 1)
        s += __shfl_xor_sync(0xffffffffu, s, off);
    if (threadIdx.x == 0)
        out[0] = (float)(s / (8192.0 * 8191.0));
}

extern "C" void kernel_launch(void* const* d_in, const int* in_sizes, int n_in,
                              void* d_out, int out_size)
{
    (void)in_sizes; (void)n_in; (void)out_size;
    const float* Q = (const float*)d_in[0];
    const float* K = (const float*)d_in[1];

    cudaFuncSetAttribute(conv_kernel,
                         cudaFuncAttributeMaxDynamicSharedMemorySize, CONV_SMEM);
    cudaFuncSetAttribute(gram_kernel,
                         cudaFuncAttributeMaxDynamicSharedMemorySize, GRAM_SMEM);

    conv_kernel<<<256, 256, CONV_SMEM>>>(Q, K);
    gram_kernel<<<192, 256, GRAM_SMEM>>>();
    reduce_kernel<<<RED_BLOCKS, 256>>>();
    final_kernel<<<1, 32>>>((float*)d_out);
}